// round 1
// baseline (speedup 1.0000x reference)
#include <cuda_runtime.h>
#include <math.h>

#define EPS 1e-5f

// ---------------- scratch (static device allocations; no runtime alloc) ------
__device__ float  g_xd[32*256*64];            // pooled input  [B,C,8,8]
__device__ float  g_h [32*256*64];            // router hidden [B,C,8,8]
__device__ int    g_eidx[64];                 // expert index per slot
__device__ float  g_wt [64];                  // (thresholded) weight per slot
__device__ float  g_y [64ULL*512*4096];       // GEMM1 out per slot [HID,HW]
__device__ float  g_z [64ULL*256*4096];       // GEMM2 out per slot [COUT,HW]
__device__ float2 g_ab1[64*512];              // per-slot GN1 scale/shift
__device__ float2 g_ab2[64*256];              // per-slot GN2 scale/shift

// ---------------- 8x8 average pool -------------------------------------------
__global__ void pool_kernel(const float* __restrict__ x) {
    int bc = blockIdx.x;           // (b*256+c)
    int p  = threadIdx.x;          // 0..63 -> (i,j)
    int i = p >> 3, j = p & 7;
    const float* base = x + (size_t)bc*4096 + i*8*64 + j*8;
    float s = 0.f;
    #pragma unroll
    for (int di = 0; di < 8; di++)
        #pragma unroll
        for (int dj = 0; dj < 8; dj++) s += base[di*64 + dj];
    g_xd[bc*64 + p] = s * (1.f/64.f);
}

// ---------------- router: depthwise 3x3 + GN(8) + SiLU ----------------------
__global__ void router_conv_kernel(const float* __restrict__ r_dw,
                                   const float* __restrict__ r_g1,
                                   const float* __restrict__ r_b1) {
    int b = blockIdx.x, c = threadIdx.x;      // 256 threads = channels
    const float* xd = g_xd + (b*256 + c)*64;
    float wv[9];
    #pragma unroll
    for (int i = 0; i < 9; i++) wv[i] = r_dw[c*9 + i];
    float o[64]; float s = 0.f, q = 0.f;
    #pragma unroll
    for (int i = 0; i < 8; i++)
        #pragma unroll
        for (int j = 0; j < 8; j++) {
            float a = 0.f;
            #pragma unroll
            for (int di = -1; di <= 1; di++) {
                int ii = i + di; if (ii < 0 || ii > 7) continue;
                #pragma unroll
                for (int dj = -1; dj <= 1; dj++) {
                    int jj = j + dj; if (jj < 0 || jj > 7) continue;
                    a += xd[ii*8 + jj] * wv[(di+1)*3 + (dj+1)];
                }
            }
            o[i*8 + j] = a; s += a; q += a*a;
        }
    // group == warp (32 channels per group, 8 groups over 256 channels)
    #pragma unroll
    for (int off = 16; off > 0; off >>= 1) {
        s += __shfl_xor_sync(0xffffffffu, s, off);
        q += __shfl_xor_sync(0xffffffffu, q, off);
    }
    float mean = s * (1.f/2048.f);
    float var  = q * (1.f/2048.f) - mean*mean;
    float rstd = rsqrtf(var + EPS);
    float ga = r_g1[c], be = r_b1[c];
    float* outp = g_h + (b*256 + c)*64;
    #pragma unroll
    for (int p = 0; p < 64; p++) {
        float v = (o[p] - mean) * rstd * ga + be;
        outp[p] = v / (1.f + expf(-v));
    }
}

// ---------------- router: 1x1->GN(4)->SiLU->1x1->softmax->pool->top2 ---------
__global__ void router_rest_kernel(const float* __restrict__ r_pw1,
                                   const float* __restrict__ r_g2,
                                   const float* __restrict__ r_b2,
                                   const float* __restrict__ r_pw2,
                                   const float* __restrict__ r_pb2) {
    int b = blockIdx.x, t = threadIdx.x;
    __shared__ float h2[1024];     // [16][64]
    __shared__ float lg[512];      // [8][64] logits -> weights
    __shared__ float pooled[8];
    __shared__ float gmean[4], grstd[4];
    const float* H = g_h + b*256*64;

    for (int o = t; o < 1024; o += 256) {
        int r = o >> 6, p = o & 63;
        float a = 0.f;
        for (int c = 0; c < 256; c++) a += r_pw1[r*256 + c] * H[c*64 + p];
        h2[o] = a;
    }
    __syncthreads();
    if (t < 4) {                   // group t: channels 4t..4t+3, contiguous 256 elems
        float s = 0.f, q = 0.f;
        for (int i = 0; i < 256; i++) { float v = h2[t*256 + i]; s += v; q += v*v; }
        float m = s * (1.f/256.f);
        gmean[t] = m; grstd[t] = rsqrtf(q * (1.f/256.f) - m*m + EPS);
    }
    __syncthreads();
    for (int o = t; o < 1024; o += 256) {
        int r = o >> 6, g = r >> 2;
        float v = (h2[o] - gmean[g]) * grstd[g] * r_g2[r] + r_b2[r];
        h2[o] = v / (1.f + expf(-v));
    }
    __syncthreads();
    for (int o = t; o < 512; o += 256) {
        int e = o >> 6, p = o & 63;
        float a = r_pb2[e];
        #pragma unroll
        for (int r = 0; r < 16; r++) a += r_pw2[e*16 + r] * h2[r*64 + p];
        lg[o] = a;
    }
    __syncthreads();
    if (t < 64) {                  // softmax over E per spatial position
        int p = t;
        float m = -1e30f;
        #pragma unroll
        for (int e = 0; e < 8; e++) m = fmaxf(m, lg[e*64 + p]);
        float ex[8], s = 0.f;
        #pragma unroll
        for (int e = 0; e < 8; e++) { ex[e] = expf(lg[e*64 + p] - m); s += ex[e]; }
        float inv = 1.f / s;
        #pragma unroll
        for (int e = 0; e < 8; e++) lg[e*64 + p] = ex[e] * inv;
    }
    __syncthreads();
    if (t < 8) {                   // deterministic spatial mean
        float s = 0.f;
        for (int p = 0; p < 64; p++) s += lg[t*64 + p];
        pooled[t] = s * (1.f/64.f);
    }
    __syncthreads();
    if (t == 0) {                  // top-2, lowest index wins ties (matches lax.top_k)
        int i1 = 0;
        for (int e = 1; e < 8; e++) if (pooled[e] > pooled[i1]) i1 = e;
        int i2 = (i1 == 0) ? 1 : 0;
        for (int e = 0; e < 8; e++) if (e != i1 && pooled[e] > pooled[i2]) i2 = e;
        float v1 = pooled[i1], v2 = pooled[i2];
        float sm = v1 + v2 + 1e-9f;
        float w1 = v1 / sm, w2 = v2 / sm;
        w1 = (w1 > 0.01f) ? w1 : 0.f;
        w2 = (w2 > 0.01f) ? w2 : 0.f;
        g_eidx[2*b] = i1; g_eidx[2*b+1] = i2;
        g_wt [2*b] = w1; g_wt [2*b+1] = w2;
    }
}

// ---------------- tiled SGEMM body: C[M,4096] = A[M,K] * B[K,4096] -----------
// 128x128 block, BK=8, 256 threads, 8x8 microtile. ACT applies per-channel
// GN1 affine + SiLU to B elements on load (channel = K row).
template <int M, int K, bool ACT>
__device__ __forceinline__ void gemm_body(const float* __restrict__ A,
                                          const float* __restrict__ Bm,
                                          float* __restrict__ C,
                                          const float2* __restrict__ ab) {
    constexpr int N = 4096, BM = 128, BN = 128, BK = 8;
    __shared__ float As[BK][BM];
    __shared__ float Bs[BK][BN];
    const int tid = threadIdx.x;
    const int tr = tid >> 4, tc = tid & 15;
    const int cRow = blockIdx.y * BM, cCol = blockIdx.x * BN;
    const int aRow = tid >> 1, aCol = (tid & 1) * 4;
    const int bRow = tid >> 5, bCol = (tid & 31) * 4;

    float acc[8][8];
    #pragma unroll
    for (int i = 0; i < 8; i++)
        #pragma unroll
        for (int j = 0; j < 8; j++) acc[i][j] = 0.f;

    for (int k0 = 0; k0 < K; k0 += BK) {
        float4 av = *(const float4*)(A + (size_t)(cRow + aRow)*K + k0 + aCol);
        As[aCol+0][aRow] = av.x; As[aCol+1][aRow] = av.y;
        As[aCol+2][aRow] = av.z; As[aCol+3][aRow] = av.w;

        float4 bv = *(const float4*)(Bm + (size_t)(k0 + bRow)*N + cCol + bCol);
        if (ACT) {
            float2 sc = ab[k0 + bRow];
            float u;
            u = bv.x*sc.x + sc.y; bv.x = u / (1.f + __expf(-u));
            u = bv.y*sc.x + sc.y; bv.y = u / (1.f + __expf(-u));
            u = bv.z*sc.x + sc.y; bv.z = u / (1.f + __expf(-u));
            u = bv.w*sc.x + sc.y; bv.w = u / (1.f + __expf(-u));
        }
        *(float4*)(&Bs[bRow][bCol]) = bv;
        __syncthreads();

        float regM[8], regN[8];
        #pragma unroll
        for (int kk = 0; kk < BK; kk++) {
            #pragma unroll
            for (int i = 0; i < 8; i++) regM[i] = As[kk][tr*8 + i];
            #pragma unroll
            for (int j = 0; j < 8; j++) regN[j] = Bs[kk][tc*8 + j];
            #pragma unroll
            for (int i = 0; i < 8; i++)
                #pragma unroll
                for (int j = 0; j < 8; j++) acc[i][j] += regM[i] * regN[j];
        }
        __syncthreads();
    }
    #pragma unroll
    for (int i = 0; i < 8; i++) {
        float* crow = C + (size_t)(cRow + tr*8 + i)*N + cCol + tc*8;
        *(float4*)(crow)     = make_float4(acc[i][0], acc[i][1], acc[i][2], acc[i][3]);
        *(float4*)(crow + 4) = make_float4(acc[i][4], acc[i][5], acc[i][6], acc[i][7]);
    }
}

__global__ void gemm1_kernel(const float* __restrict__ x,
                             const float* __restrict__ e_w1) {
    int slot = blockIdx.z;
    if (g_wt[slot] == 0.f) return;
    int e = g_eidx[slot];
    gemm_body<512, 256, false>(e_w1 + (size_t)e*512*256,
                               x + (size_t)(slot >> 1)*256*4096,
                               g_y + (size_t)slot*512*4096, nullptr);
}

__global__ void gemm2_kernel(const float* __restrict__ e_w2) {
    int slot = blockIdx.z;
    if (g_wt[slot] == 0.f) return;
    int e = g_eidx[slot];
    gemm_body<256, 512, true>(e_w2 + (size_t)e*256*512,
                              g_y + (size_t)slot*512*4096,
                              g_z + (size_t)slot*256*4096,
                              g_ab1 + slot*512);
}

// ---------------- GN stats over GEMM1 output (8 groups x 64 ch) --------------
__global__ void gn1_stats_kernel(const float* __restrict__ e_g1,
                                 const float* __restrict__ e_b1) {
    int g = blockIdx.x, slot = blockIdx.y;
    if (g_wt[slot] == 0.f) return;
    const float4* Y = (const float4*)(g_y + (size_t)slot*512*4096 + (size_t)g*64*4096);
    const int n4 = 64*4096/4;
    float s = 0.f, q = 0.f;
    for (int i = threadIdx.x; i < n4; i += 256) {
        float4 v = Y[i];
        s += v.x + v.y + v.z + v.w;
        q += v.x*v.x + v.y*v.y + v.z*v.z + v.w*v.w;
    }
    __shared__ float ss[256], sq[256];
    ss[threadIdx.x] = s; sq[threadIdx.x] = q; __syncthreads();
    for (int off = 128; off > 0; off >>= 1) {
        if (threadIdx.x < off) {
            ss[threadIdx.x] += ss[threadIdx.x + off];
            sq[threadIdx.x] += sq[threadIdx.x + off];
        }
        __syncthreads();
    }
    float mean = ss[0] * (1.f/262144.f);
    float var  = sq[0] * (1.f/262144.f) - mean*mean;
    float rstd = rsqrtf(var + EPS);
    if (threadIdx.x < 64) {
        int c = g*64 + threadIdx.x;
        int e = g_eidx[slot];
        float sc = rstd * e_g1[e*512 + c];
        g_ab1[slot*512 + c] = make_float2(sc, e_b1[e*512 + c] - mean*sc);
    }
}

// ---------------- GN stats over GEMM2 output (8 groups x 32 ch) --------------
__global__ void gn2_stats_kernel(const float* __restrict__ e_g2,
                                 const float* __restrict__ e_b2) {
    int g = blockIdx.x, slot = blockIdx.y;
    if (g_wt[slot] == 0.f) return;
    const float4* Z = (const float4*)(g_z + (size_t)slot*256*4096 + (size_t)g*32*4096);
    const int n4 = 32*4096/4;
    float s = 0.f, q = 0.f;
    for (int i = threadIdx.x; i < n4; i += 256) {
        float4 v = Z[i];
        s += v.x + v.y + v.z + v.w;
        q += v.x*v.x + v.y*v.y + v.z*v.z + v.w*v.w;
    }
    __shared__ float ss[256], sq[256];
    ss[threadIdx.x] = s; sq[threadIdx.x] = q; __syncthreads();
    for (int off = 128; off > 0; off >>= 1) {
        if (threadIdx.x < off) {
            ss[threadIdx.x] += ss[threadIdx.x + off];
            sq[threadIdx.x] += sq[threadIdx.x + off];
        }
        __syncthreads();
    }
    float mean = ss[0] * (1.f/131072.f);
    float var  = sq[0] * (1.f/131072.f) - mean*mean;
    float rstd = rsqrtf(var + EPS);
    if (threadIdx.x < 32) {
        int c = g*32 + threadIdx.x;
        int e = g_eidx[slot];
        float sc = rstd * e_g2[e*256 + c];
        g_ab2[slot*256 + c] = make_float2(sc, e_b2[e*256 + c] - mean*sc);
    }
}

// ---------------- final: out[b] = sum_k w_k * (GN2 affine of z_k) ------------
__global__ void combine_kernel(float* __restrict__ out) {
    size_t idx = ((size_t)blockIdx.x*256 + threadIdx.x) * 4;   // elem index
    int b   = (int)(idx >> 20);            // 256*4096 = 2^20 elems per image
    int rem = (int)(idx & 1048575);
    int c   = rem >> 12;
    float4 o = make_float4(0.f, 0.f, 0.f, 0.f);
    #pragma unroll
    for (int k = 0; k < 2; k++) {
        int slot = 2*b + k;
        float w = g_wt[slot];
        if (w != 0.f) {
            float2 ss = g_ab2[slot*256 + c];
            float4 z = *(const float4*)(g_z + (size_t)slot*1048576 + rem);
            o.x += w * (z.x*ss.x + ss.y);
            o.y += w * (z.y*ss.x + ss.y);
            o.z += w * (z.z*ss.x + ss.y);
            o.w += w * (z.w*ss.x + ss.y);
        }
    }
    *(float4*)(out + idx) = o;
}

// ---------------- launch ------------------------------------------------------
extern "C" void kernel_launch(void* const* d_in, const int* in_sizes, int n_in,
                              void* d_out, int out_size) {
    const float* x     = (const float*)d_in[0];
    const float* r_dw  = (const float*)d_in[1];
    const float* r_g1  = (const float*)d_in[2];
    const float* r_b1  = (const float*)d_in[3];
    const float* r_pw1 = (const float*)d_in[4];
    const float* r_g2  = (const float*)d_in[5];
    const float* r_b2  = (const float*)d_in[6];
    const float* r_pw2 = (const float*)d_in[7];
    const float* r_pb2 = (const float*)d_in[8];
    const float* e_w1  = (const float*)d_in[9];
    const float* e_g1  = (const float*)d_in[10];
    const float* e_b1  = (const float*)d_in[11];
    const float* e_w2  = (const float*)d_in[12];
    const float* e_g2  = (const float*)d_in[13];
    const float* e_b2  = (const float*)d_in[14];
    float* out = (float*)d_out;

    pool_kernel        <<<32*256, 64>>>(x);
    router_conv_kernel <<<32, 256>>>(r_dw, r_g1, r_b1);
    router_rest_kernel <<<32, 256>>>(r_pw1, r_g2, r_b2, r_pw2, r_pb2);
    gemm1_kernel       <<<dim3(32, 4, 64), 256>>>(x, e_w1);
    gn1_stats_kernel   <<<dim3(8, 64), 256>>>(e_g1, e_b1);
    gemm2_kernel       <<<dim3(32, 2, 64), 256>>>(e_w2);
    gn2_stats_kernel   <<<dim3(8, 64), 256>>>(e_g2, e_b2);
    combine_kernel     <<<32768, 256>>>(out);
}

// round 3
// speedup vs baseline: 1.1107x; 1.1107x over previous
#include <cuda_runtime.h>
#include <math.h>

#define EPS 1e-5f

// ---------------- scratch (static device allocations; no runtime alloc) ------
__device__ float  g_xd[32*256*64];            // pooled input  [B,C,8,8]
__device__ float  g_h [32*256*64];            // router hidden [B,C,8,8]
__device__ int    g_eidx[64];                 // expert index per slot
__device__ float  g_wt [64];                  // (thresholded) weight per slot
__device__ float  g_y [64ULL*512*4096];       // GEMM1 out per slot [HID,HW]
__device__ float  g_z [64ULL*256*4096];       // GEMM2 out per slot [COUT,HW]
__device__ float2 g_ab1[64*512];              // per-slot GN1 scale/shift
__device__ float2 g_ab2[64*256];              // per-slot GN2 scale/shift

// ---------------- 8x8 average pool -------------------------------------------
__global__ void pool_kernel(const float* __restrict__ x) {
    int bc = blockIdx.x;           // (b*256+c)
    int p  = threadIdx.x;          // 0..63 -> (i,j)
    int i = p >> 3, j = p & 7;
    const float* base = x + (size_t)bc*4096 + i*8*64 + j*8;
    float s = 0.f;
    #pragma unroll
    for (int di = 0; di < 8; di++)
        #pragma unroll
        for (int dj = 0; dj < 8; dj++) s += base[di*64 + dj];
    g_xd[bc*64 + p] = s * (1.f/64.f);
}

// ---------------- router: depthwise 3x3 + GN(8) + SiLU ----------------------
__global__ void router_conv_kernel(const float* __restrict__ r_dw,
                                   const float* __restrict__ r_g1,
                                   const float* __restrict__ r_b1) {
    int b = blockIdx.x, c = threadIdx.x;      // 256 threads = channels
    const float* xd = g_xd + (b*256 + c)*64;
    float wv[9];
    #pragma unroll
    for (int i = 0; i < 9; i++) wv[i] = r_dw[c*9 + i];
    float o[64]; float s = 0.f, q = 0.f;
    #pragma unroll
    for (int i = 0; i < 8; i++)
        #pragma unroll
        for (int j = 0; j < 8; j++) {
            float a = 0.f;
            #pragma unroll
            for (int di = -1; di <= 1; di++) {
                int ii = i + di; if (ii < 0 || ii > 7) continue;
                #pragma unroll
                for (int dj = -1; dj <= 1; dj++) {
                    int jj = j + dj; if (jj < 0 || jj > 7) continue;
                    a += xd[ii*8 + jj] * wv[(di+1)*3 + (dj+1)];
                }
            }
            o[i*8 + j] = a; s += a; q += a*a;
        }
    // group == warp (32 channels per group, 8 groups over 256 channels)
    #pragma unroll
    for (int off = 16; off > 0; off >>= 1) {
        s += __shfl_xor_sync(0xffffffffu, s, off);
        q += __shfl_xor_sync(0xffffffffu, q, off);
    }
    float mean = s * (1.f/2048.f);
    float var  = q * (1.f/2048.f) - mean*mean;
    float rstd = rsqrtf(var + EPS);
    float ga = r_g1[c], be = r_b1[c];
    float* outp = g_h + (b*256 + c)*64;
    #pragma unroll
    for (int p = 0; p < 64; p++) {
        float v = (o[p] - mean) * rstd * ga + be;
        outp[p] = v / (1.f + expf(-v));
    }
}

// ---------------- router: 1x1->GN(4)->SiLU->1x1->softmax->pool->top2 ---------
__global__ void router_rest_kernel(const float* __restrict__ r_pw1,
                                   const float* __restrict__ r_g2,
                                   const float* __restrict__ r_b2,
                                   const float* __restrict__ r_pw2,
                                   const float* __restrict__ r_pb2) {
    int b = blockIdx.x, t = threadIdx.x;
    __shared__ float h2[1024];     // [16][64]
    __shared__ float lg[512];      // [8][64] logits -> weights
    __shared__ float pooled[8];
    __shared__ float gmean[4], grstd[4];
    const float* H = g_h + b*256*64;

    for (int o = t; o < 1024; o += 256) {
        int r = o >> 6, p = o & 63;
        float a = 0.f;
        for (int c = 0; c < 256; c++) a += r_pw1[r*256 + c] * H[c*64 + p];
        h2[o] = a;
    }
    __syncthreads();
    if (t < 4) {                   // group t: channels 4t..4t+3, contiguous 256 elems
        float s = 0.f, q = 0.f;
        for (int i = 0; i < 256; i++) { float v = h2[t*256 + i]; s += v; q += v*v; }
        float m = s * (1.f/256.f);
        gmean[t] = m; grstd[t] = rsqrtf(q * (1.f/256.f) - m*m + EPS);
    }
    __syncthreads();
    for (int o = t; o < 1024; o += 256) {
        int r = o >> 6, g = r >> 2;
        float v = (h2[o] - gmean[g]) * grstd[g] * r_g2[r] + r_b2[r];
        h2[o] = v / (1.f + expf(-v));
    }
    __syncthreads();
    for (int o = t; o < 512; o += 256) {
        int e = o >> 6, p = o & 63;
        float a = r_pb2[e];
        #pragma unroll
        for (int r = 0; r < 16; r++) a += r_pw2[e*16 + r] * h2[r*64 + p];
        lg[o] = a;
    }
    __syncthreads();
    if (t < 64) {                  // softmax over E per spatial position
        int p = t;
        float m = -1e30f;
        #pragma unroll
        for (int e = 0; e < 8; e++) m = fmaxf(m, lg[e*64 + p]);
        float ex[8], s = 0.f;
        #pragma unroll
        for (int e = 0; e < 8; e++) { ex[e] = expf(lg[e*64 + p] - m); s += ex[e]; }
        float inv = 1.f / s;
        #pragma unroll
        for (int e = 0; e < 8; e++) lg[e*64 + p] = ex[e] * inv;
    }
    __syncthreads();
    if (t < 8) {                   // deterministic spatial mean
        float s = 0.f;
        for (int p = 0; p < 64; p++) s += lg[t*64 + p];
        pooled[t] = s * (1.f/64.f);
    }
    __syncthreads();
    if (t == 0) {                  // top-2, lowest index wins ties (matches lax.top_k)
        int i1 = 0;
        for (int e = 1; e < 8; e++) if (pooled[e] > pooled[i1]) i1 = e;
        int i2 = (i1 == 0) ? 1 : 0;
        for (int e = 0; e < 8; e++) if (e != i1 && pooled[e] > pooled[i2]) i2 = e;
        float v1 = pooled[i1], v2 = pooled[i2];
        float sm = v1 + v2 + 1e-9f;
        float w1 = v1 / sm, w2 = v2 / sm;
        w1 = (w1 > 0.01f) ? w1 : 0.f;
        w2 = (w2 > 0.01f) ? w2 : 0.f;
        g_eidx[2*b] = i1; g_eidx[2*b+1] = i2;
        g_wt [2*b] = w1; g_wt [2*b+1] = w2;
    }
}

// ---------------- pipelined SGEMM: C[M,4096] = A[M,K] * B[K,4096] ------------
// 128x128 block, BK=16, 256 threads, 8x8 microtile, double-buffered smem with
// register-staged global prefetch. ACT applies per-channel GN1 affine + SiLU
// to B elements on load (channel = K row).
template <int M, int K, bool ACT>
__device__ __forceinline__ void gemm_body(const float* __restrict__ A,
                                          const float* __restrict__ Bm,
                                          float* __restrict__ C,
                                          const float2* __restrict__ ab) {
    constexpr int N = 4096, BM = 128, BN = 128, BK = 16;
    __shared__ float As[2][BK][BM];
    __shared__ float Bs[2][BK][BN];
    const int tid = threadIdx.x;
    const int tr = tid >> 4, tc = tid & 15;
    const int cRow = blockIdx.y * BM, cCol = blockIdx.x * BN;

    // A tile: 128 rows x 16 cols = 512 float4; 2 per thread
    const int aRow0 = tid >> 2,          aCol0 = (tid & 3) * 4;
    const int aRow1 = (tid + 256) >> 2,  aCol1 = aCol0;
    // B tile: 16 rows x 128 cols = 512 float4; 2 per thread
    const int bRow0 = tid >> 5,          bCol0 = (tid & 31) * 4;
    const int bRow1 = (tid + 256) >> 5,  bCol1 = bCol0;

    float acc[8][8];
    #pragma unroll
    for (int i = 0; i < 8; i++)
        #pragma unroll
        for (int j = 0; j < 8; j++) acc[i][j] = 0.f;

    float4 aReg0, aReg1, bReg0, bReg1;

    auto load_g = [&](int k0) {
        aReg0 = *(const float4*)(A + (size_t)(cRow + aRow0)*K + k0 + aCol0);
        aReg1 = *(const float4*)(A + (size_t)(cRow + aRow1)*K + k0 + aCol1);
        bReg0 = *(const float4*)(Bm + (size_t)(k0 + bRow0)*N + cCol + bCol0);
        bReg1 = *(const float4*)(Bm + (size_t)(k0 + bRow1)*N + cCol + bCol1);
        if (ACT) {
            float2 s0 = ab[k0 + bRow0], s1 = ab[k0 + bRow1];
            float u;
            u = bReg0.x*s0.x + s0.y; bReg0.x = u / (1.f + __expf(-u));
            u = bReg0.y*s0.x + s0.y; bReg0.y = u / (1.f + __expf(-u));
            u = bReg0.z*s0.x + s0.y; bReg0.z = u / (1.f + __expf(-u));
            u = bReg0.w*s0.x + s0.y; bReg0.w = u / (1.f + __expf(-u));
            u = bReg1.x*s1.x + s1.y; bReg1.x = u / (1.f + __expf(-u));
            u = bReg1.y*s1.x + s1.y; bReg1.y = u / (1.f + __expf(-u));
            u = bReg1.z*s1.x + s1.y; bReg1.z = u / (1.f + __expf(-u));
            u = bReg1.w*s1.x + s1.y; bReg1.w = u / (1.f + __expf(-u));
        }
    };
    auto store_s = [&](int buf) {
        As[buf][aCol0+0][aRow0] = aReg0.x; As[buf][aCol0+1][aRow0] = aReg0.y;
        As[buf][aCol0+2][aRow0] = aReg0.z; As[buf][aCol0+3][aRow0] = aReg0.w;
        As[buf][aCol1+0][aRow1] = aReg1.x; As[buf][aCol1+1][aRow1] = aReg1.y;
        As[buf][aCol1+2][aRow1] = aReg1.z; As[buf][aCol1+3][aRow1] = aReg1.w;
        *(float4*)(&Bs[buf][bRow0][bCol0]) = bReg0;
        *(float4*)(&Bs[buf][bRow1][bCol1]) = bReg1;
    };

    load_g(0);
    store_s(0);
    __syncthreads();

    int buf = 0;
    for (int k0 = 0; k0 < K; k0 += BK) {
        const bool last = (k0 + BK >= K);
        if (!last) load_g(k0 + BK);            // LDG in flight during compute
        #pragma unroll
        for (int kk = 0; kk < BK; kk++) {
            float4 m0 = *(const float4*)(&As[buf][kk][tr*8]);
            float4 m1 = *(const float4*)(&As[buf][kk][tr*8 + 4]);
            float4 n0 = *(const float4*)(&Bs[buf][kk][tc*8]);
            float4 n1 = *(const float4*)(&Bs[buf][kk][tc*8 + 4]);
            float rm[8] = {m0.x,m0.y,m0.z,m0.w,m1.x,m1.y,m1.z,m1.w};
            float rn[8] = {n0.x,n0.y,n0.z,n0.w,n1.x,n1.y,n1.z,n1.w};
            #pragma unroll
            for (int i = 0; i < 8; i++)
                #pragma unroll
                for (int j = 0; j < 8; j++) acc[i][j] += rm[i] * rn[j];
        }
        if (!last) {
            store_s(buf ^ 1);
            __syncthreads();
            buf ^= 1;
        }
    }

    #pragma unroll
    for (int i = 0; i < 8; i++) {
        float* crow = C + (size_t)(cRow + tr*8 + i)*N + cCol + tc*8;
        *(float4*)(crow)     = make_float4(acc[i][0], acc[i][1], acc[i][2], acc[i][3]);
        *(float4*)(crow + 4) = make_float4(acc[i][4], acc[i][5], acc[i][6], acc[i][7]);
    }
}

__global__ void __launch_bounds__(256, 2)
gemm1_kernel(const float* __restrict__ x, const float* __restrict__ e_w1) {
    int slot = blockIdx.z;
    if (g_wt[slot] == 0.f) return;
    int e = g_eidx[slot];
    gemm_body<512, 256, false>(e_w1 + (size_t)e*512*256,
                               x + (size_t)(slot >> 1)*256*4096,
                               g_y + (size_t)slot*512*4096, nullptr);
}

__global__ void __launch_bounds__(256, 2)
gemm2_kernel(const float* __restrict__ e_w2) {
    int slot = blockIdx.z;
    if (g_wt[slot] == 0.f) return;
    int e = g_eidx[slot];
    gemm_body<256, 512, true>(e_w2 + (size_t)e*256*512,
                              g_y + (size_t)slot*512*4096,
                              g_z + (size_t)slot*256*4096,
                              g_ab1 + slot*512);
}

// ---------------- GN stats over GEMM1 output (8 groups x 64 ch) --------------
__global__ void gn1_stats_kernel(const float* __restrict__ e_g1,
                                 const float* __restrict__ e_b1) {
    int g = blockIdx.x, slot = blockIdx.y;
    if (g_wt[slot] == 0.f) return;
    const float4* Y = (const float4*)(g_y + (size_t)slot*512*4096 + (size_t)g*64*4096);
    const int n4 = 64*4096/4;
    float s = 0.f, q = 0.f;
    for (int i = threadIdx.x; i < n4; i += 256) {
        float4 v = Y[i];
        s += v.x + v.y + v.z + v.w;
        q += v.x*v.x + v.y*v.y + v.z*v.z + v.w*v.w;
    }
    __shared__ float ss[256], sq[256];
    ss[threadIdx.x] = s; sq[threadIdx.x] = q; __syncthreads();
    for (int off = 128; off > 0; off >>= 1) {
        if (threadIdx.x < off) {
            ss[threadIdx.x] += ss[threadIdx.x + off];
            sq[threadIdx.x] += sq[threadIdx.x + off];
        }
        __syncthreads();
    }
    float mean = ss[0] * (1.f/262144.f);
    float var  = sq[0] * (1.f/262144.f) - mean*mean;
    float rstd = rsqrtf(var + EPS);
    if (threadIdx.x < 64) {
        int c = g*64 + threadIdx.x;
        int e = g_eidx[slot];
        float sc = rstd * e_g1[e*512 + c];
        g_ab1[slot*512 + c] = make_float2(sc, e_b1[e*512 + c] - mean*sc);
    }
}

// ---------------- GN stats over GEMM2 output (8 groups x 32 ch) --------------
__global__ void gn2_stats_kernel(const float* __restrict__ e_g2,
                                 const float* __restrict__ e_b2) {
    int g = blockIdx.x, slot = blockIdx.y;
    if (g_wt[slot] == 0.f) return;
    const float4* Z = (const float4*)(g_z + (size_t)slot*256*4096 + (size_t)g*32*4096);
    const int n4 = 32*4096/4;
    float s = 0.f, q = 0.f;
    for (int i = threadIdx.x; i < n4; i += 256) {
        float4 v = Z[i];
        s += v.x + v.y + v.z + v.w;
        q += v.x*v.x + v.y*v.y + v.z*v.z + v.w*v.w;
    }
    __shared__ float ss[256], sq[256];
    ss[threadIdx.x] = s; sq[threadIdx.x] = q; __syncthreads();
    for (int off = 128; off > 0; off >>= 1) {
        if (threadIdx.x < off) {
            ss[threadIdx.x] += ss[threadIdx.x + off];
            sq[threadIdx.x] += sq[threadIdx.x + off];
        }
        __syncthreads();
    }
    float mean = ss[0] * (1.f/131072.f);
    float var  = sq[0] * (1.f/131072.f) - mean*mean;
    float rstd = rsqrtf(var + EPS);
    if (threadIdx.x < 32) {
        int c = g*32 + threadIdx.x;
        int e = g_eidx[slot];
        float sc = rstd * e_g2[e*256 + c];
        g_ab2[slot*256 + c] = make_float2(sc, e_b2[e*256 + c] - mean*sc);
    }
}

// ---------------- final: out[b] = sum_k w_k * (GN2 affine of z_k) ------------
__global__ void combine_kernel(float* __restrict__ out) {
    size_t idx = ((size_t)blockIdx.x*256 + threadIdx.x) * 4;   // elem index
    int b   = (int)(idx >> 20);            // 256*4096 = 2^20 elems per image
    int rem = (int)(idx & 1048575);
    int c   = rem >> 12;
    float4 o = make_float4(0.f, 0.f, 0.f, 0.f);
    #pragma unroll
    for (int k = 0; k < 2; k++) {
        int slot = 2*b + k;
        float w = g_wt[slot];
        if (w != 0.f) {
            float2 ss = g_ab2[slot*256 + c];
            float4 z = *(const float4*)(g_z + (size_t)slot*1048576 + rem);
            o.x += w * (z.x*ss.x + ss.y);
            o.y += w * (z.y*ss.x + ss.y);
            o.z += w * (z.z*ss.x + ss.y);
            o.w += w * (z.w*ss.x + ss.y);
        }
    }
    *(float4*)(out + idx) = o;
}

// ---------------- launch ------------------------------------------------------
extern "C" void kernel_launch(void* const* d_in, const int* in_sizes, int n_in,
                              void* d_out, int out_size) {
    const float* x     = (const float*)d_in[0];
    const float* r_dw  = (const float*)d_in[1];
    const float* r_g1  = (const float*)d_in[2];
    const float* r_b1  = (const float*)d_in[3];
    const float* r_pw1 = (const float*)d_in[4];
    const float* r_g2  = (const float*)d_in[5];
    const float* r_b2  = (const float*)d_in[6];
    const float* r_pw2 = (const float*)d_in[7];
    const float* r_pb2 = (const float*)d_in[8];
    const float* e_w1  = (const float*)d_in[9];
    const float* e_g1  = (const float*)d_in[10];
    const float* e_b1  = (const float*)d_in[11];
    const float* e_w2  = (const float*)d_in[12];
    const float* e_g2  = (const float*)d_in[13];
    const float* e_b2  = (const float*)d_in[14];
    float* out = (float*)d_out;

    pool_kernel        <<<32*256, 64>>>(x);
    router_conv_kernel <<<32, 256>>>(r_dw, r_g1, r_b1);
    router_rest_kernel <<<32, 256>>>(r_pw1, r_g2, r_b2, r_pw2, r_pb2);
    gemm1_kernel       <<<dim3(32, 4, 64), 256>>>(x, e_w1);
    gn1_stats_kernel   <<<dim3(8, 64), 256>>>(e_g1, e_b1);
    gemm2_kernel       <<<dim3(32, 2, 64), 256>>>(e_w2);
    gn2_stats_kernel   <<<dim3(8, 64), 256>>>(e_g2, e_b2);
    combine_kernel     <<<32768, 256>>>(out);
}